// round 10
// baseline (speedup 1.0000x reference)
#include <cuda_runtime.h>
#include <math.h>
#include <stdint.h>

#define B_    64
#define T_    1000
#define D_    512
#define V_    29
#define L_    200
#define S_    401            // 2*L + 1
#define CBLANK 28
#define NEGV  (-1e9f)
#define LOG2E 1.44269504088896340736f
#define LN2   0.69314718055994530942f

typedef unsigned long long u64;

// ---------------- device scratch (no allocations allowed) ----------------
__device__ float d_lp[(long)B_ * T_ * V_];   // LOG2-probs lp2[b][t][v], 7.4 MB
__device__ float d_loss[B_];

__device__ __forceinline__ float ex2f(float x){ float r; asm("ex2.approx.f32 %0, %1;" : "=f"(r) : "f"(x)); return r; }
__device__ __forceinline__ float lg2f(float x){ float r; asm("lg2.approx.f32 %0, %1;" : "=f"(r) : "f"(x)); return r; }

// exact 3-way log2-sum-exp via selects (no cancellation; NEGV-safe)
__device__ __forceinline__ float lse3(float a0, float a1, float a2)
{
    const float mab = fmaxf(a0, a1);
    const float nab = fminf(a0, a1);
    const float mx  = fmaxf(mab, a2);
    const float mn  = fminf(nab, a2);
    const float md  = fmaxf(nab, fminf(mab, a2));
    return mx + lg2f(1.0f + ex2f(mn - mx) + ex2f(md - mx));
}
// 2-way log2-sum-exp (blank states never take the skip transition)
__device__ __forceinline__ float lse2(float a0, float a1)
{
    const float mx = fmaxf(a0, a1);
    const float mn = fminf(a0, a1);
    return mx + lg2f(1.0f + ex2f(mn - mx));
}

#define FMA2(d, a, b) asm("fma.rn.f32x2 %0, %1, %2, %0;" : "+l"(d) : "l"(a), "l"(b))

// =====================================================================
// Kernel 1: logits = F @ W + b, log2_softmax, write d_lp.  (R8 verbatim)
// 256 threads, BM=256 rows/block (grid=250), thread tile 8 rows x 4 cols.
// F: cp.async double-buffered, row-major, XOR-swizzled smem.
// W: whole 512x32 transposed wT[col][k] (stride 516), resident in smem.
// =====================================================================
#define BM2 256
#define WT_STRIDE 516
#define SMEM_GEMM_BYTES 132608

extern __shared__ char smem_dyn[];

__global__ __launch_bounds__(256, 1) void gemm_lsm_kernel(
    const float* __restrict__ F, const float* __restrict__ W,
    const float* __restrict__ bias)
{
    float* fbuf = (float*)smem_dyn;
    float* wT   = (float*)(smem_dyn + 65536);
    float* csh  = (float*)(smem_dyn + 131584);
    float* lbuf = fbuf;                         // epilogue reuse

    const int tid = threadIdx.x;
    const long rowBase = (long)blockIdx.x * BM2;
    const uint32_t fsh = (uint32_t)__cvta_generic_to_shared(fbuf);

    auto prefetch = [&](int kci, int st) {
        const uint32_t sbase = fsh + st * 32768u;
#pragma unroll
        for (int m = 0; m < 8; m++) {
            const int q  = tid + 256 * m;
            const int r  = q >> 3;
            const int kq = q & 7;
            const float* src = F + (rowBase + r) * D_ + kci * 32 + kq * 4;
            const uint32_t dst = sbase + (uint32_t)((r * 32 + ((kq ^ ((r >> 3) & 7)) << 2)) * 4);
            asm volatile("cp.async.ca.shared.global [%0], [%1], 16;" :: "r"(dst), "l"(src));
        }
    };

    prefetch(0, 0);
    asm volatile("cp.async.commit_group;");

    for (int idx = tid; idx < 512 * 32; idx += 256) {
        const int k = idx >> 5, c = idx & 31;
        wT[c * WT_STRIDE + k] = (c < V_) ? W[(long)k * V_ + c] : 0.f;
    }

    const int rg = tid >> 3;
    const int cg = tid & 7;
    const int fkey = (rg & 7) << 2;

    float bv[4];
#pragma unroll
    for (int j = 0; j < 4; j++) { int c = cg + 8 * j; bv[j] = (c < V_) ? bias[c] : 0.f; }

    u64 acc[8][4];
#pragma unroll
    for (int i = 0; i < 8; i++)
#pragma unroll
        for (int j = 0; j < 4; j++) acc[i][j] = 0ull;

    for (int kci = 0; kci < 16; kci++) {
        if (kci < 15) prefetch(kci + 1, (kci + 1) & 1);
        asm volatile("cp.async.commit_group;");
        asm volatile("cp.async.wait_group 1;");
        __syncthreads();

        const float* fstage = fbuf + (kci & 1) * 8192;
        const float* wbase  = wT + kci * 32;
#pragma unroll
        for (int kq = 0; kq < 8; kq++) {
            ulonglong2 f[8], w4[4];
#pragma unroll
            for (int i = 0; i < 8; i++)
                f[i] = *reinterpret_cast<const ulonglong2*>(
                    fstage + (rg * 8 + i) * 32 + ((kq << 2) ^ fkey));
#pragma unroll
            for (int j = 0; j < 4; j++)
                w4[j] = *reinterpret_cast<const ulonglong2*>(
                    wbase + (cg + 8 * j) * WT_STRIDE + kq * 4);
#pragma unroll
            for (int i = 0; i < 8; i++)
#pragma unroll
                for (int j = 0; j < 4; j++) FMA2(acc[i][j], f[i].x, w4[j].x);
#pragma unroll
            for (int i = 0; i < 8; i++)
#pragma unroll
                for (int j = 0; j < 4; j++) FMA2(acc[i][j], f[i].y, w4[j].y);
        }
        __syncthreads();
    }

#pragma unroll
    for (int i = 0; i < 8; i++)
#pragma unroll
        for (int j = 0; j < 4; j++) {
            const float lo = __uint_as_float((unsigned)(acc[i][j] & 0xffffffffull));
            const float hi = __uint_as_float((unsigned)(acc[i][j] >> 32));
            lbuf[(rg * 8 + i) * 33 + (cg + 8 * j)] = lo + hi + bv[j];
        }
    __syncthreads();

    {
        const float* r = &lbuf[tid * 33];
        float m = r[0];
#pragma unroll
        for (int v = 1; v < V_; v++) m = fmaxf(m, r[v]);
        float sum = 0.f;
#pragma unroll
        for (int v = 0; v < V_; v++) sum += ex2f((r[v] - m) * LOG2E);
        csh[tid] = m * LOG2E + lg2f(sum);
    }
    __syncthreads();

    float* outp = d_lp + rowBase * V_;
    for (int i = tid; i < BM2 * V_; i += 256) {
        const int row = i / V_;
        const int v   = i - row * V_;
        outp[i] = lbuf[row * 33 + v] * LOG2E - csh[row];
    }
}

// =====================================================================
// Kernel 2: CTC alpha recursion, LOG2 domain, 4 STATES PER THREAD.
// One block per batch, 128 threads (4 warps = 1 per SMSP).
// Thread i owns states (4i, 4i+1, 4i+2, 4i+3) = (blank, label, blank,
// label), all kept in registers. Because blanks never skip, the whole
// group needs exactly ONE neighbor value per step: alpha[4i-1] (one
// LDS.32). One cheap 4-warp barrier per step; write-back is 1 STS.128.
// lp: 3 rotating 4-deep LDG prefetch streams (blank, e1, e3).
// =====================================================================
__global__ __launch_bounds__(128) void ctc_kernel(
    const int* __restrict__ labels, const int* __restrict__ flens,
    const int* __restrict__ llens)
{
    __shared__ float4 pbuf[2][129];     // pbuf[.][i+1] = alpha[4i..4i+3]; [0]=NEGV pad
    __shared__ int    lab_sh[L_];

    const int b    = blockIdx.x;
    const int tid  = threadIdx.x;
    const int flen = flens[b];
    const int llen = llens[b];

    for (int i = tid; i < L_; i += 128) lab_sh[i] = labels[b * L_ + i];
    if (tid == 0) {
        pbuf[0][0] = make_float4(NEGV, NEGV, NEGV, NEGV);
        pbuf[1][0] = make_float4(NEGV, NEGV, NEGV, NEGV);
    }
    __syncthreads();

    const int i  = tid;                 // group index: states 4i..4i+3
    const int j1 = min(2 * i,     L_ - 1);   // label idx for state 4i+1
    const int j3 = min(2 * i + 1, L_ - 1);   // label idx for state 4i+3
    const int e1 = lab_sh[j1];
    const int e3 = lab_sh[j3];
    // skip for s=4i+1 (s>=3 iff i>=1); for s=4i+3 (always >=3)
    const bool skip1 = (i >= 1) && (e1 != lab_sh[j1 - 1]);
    const bool skip3 = (e3 != lab_sh[j3 - 1 >= 0 ? j3 - 1 : 0]) && (j3 >= 1);

    const float* lpb = d_lp + (long)b * T_ * V_;

    // t = 0 init
    float a0 = NEGV, a1 = NEGV, a2 = NEGV, a3 = NEGV;
    if (i == 0) { a0 = lpb[CBLANK]; a1 = lpb[e1]; }
    pbuf[0][i + 1] = make_float4(a0, a1, a2, a3);

    // 4-deep prefetch: three streams (blank col, e1 col, e3 col)
    float pB0 = lpb[1 * V_ + CBLANK], p10 = lpb[1 * V_ + e1], p30 = lpb[1 * V_ + e3];
    float pB1 = lpb[2 * V_ + CBLANK], p11 = lpb[2 * V_ + e1], p31 = lpb[2 * V_ + e3];
    float pB2 = lpb[3 * V_ + CBLANK], p12 = lpb[3 * V_ + e1], p32 = lpb[3 * V_ + e3];
    float pB3 = lpb[4 * V_ + CBLANK], p13 = lpb[4 * V_ + e1], p33 = lpb[4 * V_ + e3];
    __syncthreads();

    int cur = 0;
    int t = 1;

    // neighbor value alpha[4i-1] = pbuf[cur][i].w (scalar LDS)
    const float* nbw0 = &pbuf[0][i].w;
    const float* nbw1 = &pbuf[1][i].w;

#define CTC_STEP(PB, P1, P3) do {                                                \
    const float nw = cur ? *nbw1 : *nbw0;         /* alpha_{t-1}[4i-1] */        \
    const float n0 = lse2(a0, nw) + PB;           /* s=4i   blank */             \
    const float n1 = lse3(a1, a0, skip1 ? nw : NEGV) + P1;   /* s=4i+1 */        \
    const float n2 = lse2(a2, a1) + PB;           /* s=4i+2 blank */             \
    const float n3 = lse3(a3, a2, skip3 ? a1 : NEGV) + P3;   /* s=4i+3 */        \
    a0 = n0; a1 = n1; a2 = n2; a3 = n3;                                          \
    pbuf[cur ^ 1][i + 1] = make_float4(a0, a1, a2, a3);                          \
    cur ^= 1;                                                                    \
    const int tn = min(t + 4, T_ - 1) * V_;                                      \
    PB = lpb[tn + CBLANK]; P1 = lpb[tn + e1]; P3 = lpb[tn + e3];                 \
    __syncthreads();                                                             \
    t++;                                                                         \
} while (0)

    while (t + 3 < flen) {
        CTC_STEP(pB0, p10, p30); CTC_STEP(pB1, p11, p31);
        CTC_STEP(pB2, p12, p32); CTC_STEP(pB3, p13, p33);
    }
    while (t < flen) {
        CTC_STEP(pB0, p10, p30);
        pB0 = pB1; p10 = p11; p30 = p31;
        pB1 = pB2; p11 = p12; p31 = p32;
        pB2 = pB3; p12 = p13; p32 = p33;
    }
#undef CTC_STEP

    if (tid == 0) {
        const float* view = (const float*)&pbuf[cur][1];   // view[s] = alpha[s]
        const float l1 = view[2 * llen];
        const float l2 = view[2 * llen - 1];                // llen >= 50
        const float ls = lse2(l1, l2);
        const float nll = -ls * LN2;
        d_loss[b] = (nll < 5e8f) ? nll / (float)llen : 0.f;
    }
}

// =====================================================================
// Kernel 3: deterministic fixed-order mean of 64 losses
// =====================================================================
__global__ void reduce_kernel(float* __restrict__ out)
{
    const int lane = threadIdx.x;
    float v = d_loss[lane] + d_loss[lane + 32];
#pragma unroll
    for (int o = 16; o > 0; o >>= 1) v += __shfl_down_sync(0xffffffffu, v, o);
    if (lane == 0) out[0] = v * (1.f / (float)B_);
}

// =====================================================================
extern "C" void kernel_launch(void* const* d_in, const int* in_sizes, int n_in,
                              void* d_out, int out_size)
{
    (void)in_sizes; (void)n_in; (void)out_size;
    const float* F      = (const float*)d_in[0];
    const float* W      = (const float*)d_in[1];
    const float* bias   = (const float*)d_in[2];
    const int*   labels = (const int*)d_in[3];
    const int*   flens  = (const int*)d_in[4];
    const int*   llens  = (const int*)d_in[5];
    float* out = (float*)d_out;

    cudaFuncSetAttribute(gemm_lsm_kernel,
                         cudaFuncAttributeMaxDynamicSharedMemorySize, SMEM_GEMM_BYTES);

    gemm_lsm_kernel<<<(B_ * T_) / BM2, 256, SMEM_GEMM_BYTES>>>(F, W, bias);
    ctc_kernel<<<B_, 128>>>(labels, flens, llens);
    reduce_kernel<<<1, 32>>>(out);
}

// round 11
// speedup vs baseline: 1.2134x; 1.2134x over previous
#include <cuda_runtime.h>
#include <math.h>
#include <stdint.h>

#define B_    64
#define T_    1000
#define D_    512
#define V_    29
#define L_    200
#define S_    401            // 2*L + 1
#define CBLANK 28
#define NEGV  (-1e9f)
#define LOG2E 1.44269504088896340736f
#define LN2   0.69314718055994530942f
#define ESENT (-(1 << 29))   // integer-exponent sentinel ("-inf")

typedef unsigned long long u64;

// ---------------- device scratch (no allocations allowed) ----------------
__device__ float d_lp[(long)B_ * T_ * V_];   // LINEAR probs p[b][t][v], 7.4 MB
__device__ float d_loss[B_];

__device__ __forceinline__ float ex2f(float x){ float r; asm("ex2.approx.f32 %0, %1;" : "=f"(r) : "f"(x)); return r; }
__device__ __forceinline__ float lg2f(float x){ float r; asm("lg2.approx.f32 %0, %1;" : "=f"(r) : "f"(x)); return r; }

#define FMA2(d, a, b) asm("fma.rn.f32x2 %0, %1, %2, %0;" : "+l"(d) : "l"(a), "l"(b))

// =====================================================================
// Kernel 1: logits = F @ W + b, softmax, write LINEAR probs to d_lp.
// R8 structure + 4-stage cp.async pipeline (64KB in flight per CTA).
// 256 threads, BM=256 rows/block (grid=250), tile 8 rows x 4 cols,
// FFMA2 over k-pairs; W resident transposed in smem.
// =====================================================================
#define BM2 256
#define WT_STRIDE 516
// smem: fbuf 4 stages x 32KB = 131072 | wT 66048 | csh 1024
#define SMEM_GEMM_BYTES 198144

extern __shared__ char smem_dyn[];

__global__ __launch_bounds__(256, 1) void gemm_sm_kernel(
    const float* __restrict__ F, const float* __restrict__ W,
    const float* __restrict__ bias)
{
    float* fbuf = (float*)smem_dyn;
    float* wT   = (float*)(smem_dyn + 131072);
    float* csh  = (float*)(smem_dyn + 197120);
    float* lbuf = fbuf;                         // epilogue reuse

    const int tid = threadIdx.x;
    const long rowBase = (long)blockIdx.x * BM2;
    const uint32_t fsh = (uint32_t)__cvta_generic_to_shared(fbuf);

    auto prefetch = [&](int kci, int st) {
        const uint32_t sbase = fsh + (uint32_t)st * 32768u;
#pragma unroll
        for (int m = 0; m < 8; m++) {
            const int q  = tid + 256 * m;
            const int r  = q >> 3;
            const int kq = q & 7;
            const float* src = F + (rowBase + r) * D_ + kci * 32 + kq * 4;
            const uint32_t dst = sbase + (uint32_t)((r * 32 + ((kq ^ ((r >> 3) & 7)) << 2)) * 4);
            asm volatile("cp.async.ca.shared.global [%0], [%1], 16;" :: "r"(dst), "l"(src));
        }
    };

    prefetch(0, 0); asm volatile("cp.async.commit_group;");
    prefetch(1, 1); asm volatile("cp.async.commit_group;");
    prefetch(2, 2); asm volatile("cp.async.commit_group;");

    // one-time W transpose load (overlaps the first F prefetches)
    for (int idx = tid; idx < 512 * 32; idx += 256) {
        const int k = idx >> 5, c = idx & 31;
        wT[c * WT_STRIDE + k] = (c < V_) ? W[(long)k * V_ + c] : 0.f;
    }

    const int rg = tid >> 3;
    const int cg = tid & 7;
    const int fkey = (rg & 7) << 2;

    float bv[4];
#pragma unroll
    for (int j = 0; j < 4; j++) { int c = cg + 8 * j; bv[j] = (c < V_) ? bias[c] : 0.f; }

    u64 acc[8][4];
#pragma unroll
    for (int i = 0; i < 8; i++)
#pragma unroll
        for (int j = 0; j < 4; j++) acc[i][j] = 0ull;

    for (int kci = 0; kci < 16; kci++) {
        asm volatile("cp.async.wait_group 2;");
        __syncthreads();
        if (kci + 3 < 16) {
            prefetch(kci + 3, (kci + 3) & 3);
            asm volatile("cp.async.commit_group;");
        }

        const float* fstage = fbuf + (kci & 3) * 8192;
        const float* wbase  = wT + kci * 32;
#pragma unroll
        for (int kq = 0; kq < 8; kq++) {
            ulonglong2 f[8], w4[4];
#pragma unroll
            for (int i = 0; i < 8; i++)
                f[i] = *reinterpret_cast<const ulonglong2*>(
                    fstage + (rg * 8 + i) * 32 + ((kq << 2) ^ fkey));
#pragma unroll
            for (int j = 0; j < 4; j++)
                w4[j] = *reinterpret_cast<const ulonglong2*>(
                    wbase + (cg + 8 * j) * WT_STRIDE + kq * 4);
#pragma unroll
            for (int i = 0; i < 8; i++)
#pragma unroll
                for (int j = 0; j < 4; j++) FMA2(acc[i][j], f[i].x, w4[j].x);
#pragma unroll
            for (int i = 0; i < 8; i++)
#pragma unroll
                for (int j = 0; j < 4; j++) FMA2(acc[i][j], f[i].y, w4[j].y);
        }
        __syncthreads();
    }

    // ---- epilogue: combine k-pairs, bias, logits to smem [256][33] ----
#pragma unroll
    for (int i = 0; i < 8; i++)
#pragma unroll
        for (int j = 0; j < 4; j++) {
            const float lo = __uint_as_float((unsigned)(acc[i][j] & 0xffffffffull));
            const float hi = __uint_as_float((unsigned)(acc[i][j] >> 32));
            lbuf[(rg * 8 + i) * 33 + (cg + 8 * j)] = lo + hi + bv[j];
        }
    __syncthreads();

    // per-row log2-normalizer; thread <-> row
    {
        const float* r = &lbuf[tid * 33];
        float m = r[0];
#pragma unroll
        for (int v = 1; v < V_; v++) m = fmaxf(m, r[v]);
        float sum = 0.f;
#pragma unroll
        for (int v = 0; v < V_; v++) sum += ex2f((r[v] - m) * LOG2E);
        csh[tid] = m * LOG2E + lg2f(sum);
    }
    __syncthreads();

    // coalesced write of LINEAR probabilities
    float* outp = d_lp + rowBase * V_;
    for (int i = tid; i < BM2 * V_; i += 256) {
        const int row = i / V_;
        const int v   = i - row * V_;
        outp[i] = ex2f(lbuf[row * 33 + v] * LOG2E - csh[row]);
    }
}

// =====================================================================
// Kernel 2: CTC alpha recursion, EXACT LINEAR (mantissa, int-exponent)
// arithmetic -- ZERO MUFU in the loop. One block per batch, 416 threads,
// thread s owns state s as (m in [1,2), E int). Per step: int-max align,
// power-of-2 scales via bit ops, 3-term FMA sum (in [1,6)), multiply by
// linear prob, re-split exponent. R8 skeleton otherwise (barrier/step,
// 8-deep per-thread LDG prefetch).
// =====================================================================
__global__ __launch_bounds__(416) void ctc_kernel(
    const int* __restrict__ labels, const int* __restrict__ flens,
    const int* __restrict__ llens)
{
    __shared__ float2 abuf[2][420];     // [.][s+2] = {m, E as float-bits}
    __shared__ int    lab_sh[L_];

    const int b    = blockIdx.x;
    const int tid  = threadIdx.x;
    const int flen = flens[b];
    const int llen = llens[b];

    for (int i = tid; i < L_; i += 416) lab_sh[i] = labels[b * L_ + i];
    if (tid < 2) {
        const float2 pad = make_float2(1.0f, __int_as_float(ESENT));
        abuf[0][tid] = pad; abuf[1][tid] = pad;
    }
    __syncthreads();

    const int s = tid;                  // states 0..415 (401..415 dummies)
    int   ext  = CBLANK;
    bool  skip = false;
    if (s < S_ && (s & 1)) {
        const int j = s >> 1;
        ext  = lab_sh[j];
        skip = (s >= 3) ? (ext != lab_sh[j - 1]) : true;
    }

    const float* lpb = d_lp + (long)b * T_ * V_;

    // t = 0 init
    float m = 1.0f;
    int   E = ESENT;
    if (s < 2) {
        const float v = lpb[s == 0 ? CBLANK : ext];     // linear prob, normal fp32
        const unsigned bits = __float_as_uint(v);
        E = (int)(bits >> 23) - 127;
        m = __uint_as_float((bits & 0x007fffffu) | 0x3f800000u);
    }
    abuf[0][s + 2] = make_float2(m, __int_as_float(E));

    // 8-deep per-thread lp prefetch: pf_k holds row t+k at loop entry (t=1)
    float pf0 = lpb[1 * V_ + ext];
    float pf1 = lpb[2 * V_ + ext];
    float pf2 = lpb[3 * V_ + ext];
    float pf3 = lpb[4 * V_ + ext];
    float pf4 = lpb[5 * V_ + ext];
    float pf5 = lpb[6 * V_ + ext];
    float pf6 = lpb[7 * V_ + ext];
    float pf7 = lpb[8 * V_ + ext];
    __syncthreads();

    int cur = 0;
    int t = 1;

#define MKSCALE(d) __uint_as_float((unsigned)max((d) + 127, 0) << 23)

#define CTC_STEP(PF) do {                                                        \
    const float2 n1 = abuf[cur][s + 1];      /* state s-1 */                     \
    const float2 n2 = abuf[cur][s];          /* state s-2 */                     \
    const int E1 = __float_as_int(n1.y);                                         \
    const int E2 = skip ? __float_as_int(n2.y) : ESENT;                          \
    const int Emax = max(E, max(E1, E2));                                        \
    const float s0 = MKSCALE(E  - Emax);                                         \
    const float s1 = MKSCALE(E1 - Emax);                                         \
    const float s2 = MKSCALE(E2 - Emax);                                         \
    const float sum = fmaf(m, s0, fmaf(n1.x, s1, n2.x * s2));   /* in [1,6) */   \
    const float v = PF * sum;                                                    \
    const unsigned bits = __float_as_uint(v);                                    \
    E = Emax + (int)(bits >> 23) - 127;                                          \
    m = __uint_as_float((bits & 0x007fffffu) | 0x3f800000u);                     \
    abuf[cur ^ 1][s + 2] = make_float2(m, __int_as_float(E));                    \
    cur ^= 1;                                                                    \
    PF = lpb[min(t + 8, T_ - 1) * V_ + ext];                                     \
    __syncthreads();                                                             \
    t++;                                                                         \
} while (0)

    while (t + 7 < flen) {
        CTC_STEP(pf0); CTC_STEP(pf1); CTC_STEP(pf2); CTC_STEP(pf3);
        CTC_STEP(pf4); CTC_STEP(pf5); CTC_STEP(pf6); CTC_STEP(pf7);
    }
    while (t < flen) {
        CTC_STEP(pf0);
        pf0 = pf1; pf1 = pf2; pf2 = pf3; pf3 = pf4;
        pf4 = pf5; pf5 = pf6; pf6 = pf7;
    }
#undef CTC_STEP
#undef MKSCALE

    if (tid == 0) {
        const float2 v1 = abuf[cur][2 * llen + 2];   // alpha[2*llen]
        const float2 v2 = abuf[cur][2 * llen + 1];   // alpha[2*llen-1] (llen>=50)
        const float l1 = (float)__float_as_int(v1.y) + lg2f(v1.x);
        const float l2 = (float)__float_as_int(v2.y) + lg2f(v2.x);
        const float mx = fmaxf(l1, l2), mn = fminf(l1, l2);
        const float ls = mx + lg2f(1.0f + ex2f(mn - mx));
        const float nll = -ls * LN2;
        d_loss[b] = (nll < 5e8f) ? nll / (float)llen : 0.f;
    }
}

// =====================================================================
// Kernel 3: deterministic fixed-order mean of 64 losses
// =====================================================================
__global__ void reduce_kernel(float* __restrict__ out)
{
    const int lane = threadIdx.x;
    float v = d_loss[lane] + d_loss[lane + 32];
#pragma unroll
    for (int o = 16; o > 0; o >>= 1) v += __shfl_down_sync(0xffffffffu, v, o);
    if (lane == 0) out[0] = v * (1.f / (float)B_);
}

// =====================================================================
extern "C" void kernel_launch(void* const* d_in, const int* in_sizes, int n_in,
                              void* d_out, int out_size)
{
    (void)in_sizes; (void)n_in; (void)out_size;
    const float* F      = (const float*)d_in[0];
    const float* W      = (const float*)d_in[1];
    const float* bias   = (const float*)d_in[2];
    const int*   labels = (const int*)d_in[3];
    const int*   flens  = (const int*)d_in[4];
    const int*   llens  = (const int*)d_in[5];
    float* out = (float*)d_out;

    cudaFuncSetAttribute(gemm_sm_kernel,
                         cudaFuncAttributeMaxDynamicSharedMemorySize, SMEM_GEMM_BYTES);

    gemm_sm_kernel<<<(B_ * T_) / BM2, 256, SMEM_GEMM_BYTES>>>(F, W, bias);
    ctc_kernel<<<B_, 416>>>(labels, flens, llens);
    reduce_kernel<<<1, 32>>>(out);
}